// round 15
// baseline (speedup 1.0000x reference)
#include <cuda_runtime.h>
#include <cuda_bf16.h>
#include <cstdint>

#define D        128
#define K_EMB    1024
#define BM       128
#define BN       32
#define NCHUNK   (K_EMB / BN)    // 32
#define NTHREADS 256
#define NBLOCKS  256             // 32768 / BM

// dynamic smem: E double buffer 2x16KB @0, ens 4KB @32768, scratch @36864
#define EBUF(b)  ((b) * 16384)
#define OFF_ENS  32768
#define OFF_SIDX 36864           // 128 ints
#define OFF_LOSS 37376           // 8 floats + red scratch (256 floats)
#define SMEM_SZ  38656

__device__ __nv_bfloat16 g_Eh[K_EMB * D];
__device__ __nv_bfloat16 g_El[K_EMB * D];
__device__ float g_ens[K_EMB];          // 0.5*||e||^2
__device__ float g_partial[NBLOCKS];
__device__ unsigned int g_ctr;          // zero-init; self-resetting

// ---------------- helpers ----------------
__device__ __forceinline__ uint32_t smem_u32(const void* p) {
    uint32_t a;
    asm("{ .reg .u64 t; cvta.to.shared.u64 t, %1; cvt.u32.u64 %0, t; }" : "=r"(a) : "l"(p));
    return a;
}
__device__ __forceinline__ int sw(int r, int cb) {       // XOR-16B swizzle, 256B rows
    return r * 256 + (cb ^ ((r & 7) << 4));
}
__device__ __forceinline__ void ldsm4(uint32_t* r, uint32_t addr) {
    asm volatile("ldmatrix.sync.aligned.m8n8.x4.shared.b16 {%0,%1,%2,%3}, [%4];"
                 : "=r"(r[0]), "=r"(r[1]), "=r"(r[2]), "=r"(r[3]) : "r"(addr));
}
__device__ __forceinline__ void mma16816(float* c, const uint32_t* a, uint32_t b0, uint32_t b1) {
    asm volatile(
        "mma.sync.aligned.m16n8k16.row.col.f32.bf16.bf16.f32 "
        "{%0,%1,%2,%3}, {%4,%5,%6,%7}, {%8,%9}, {%0,%1,%2,%3};"
        : "+f"(c[0]), "+f"(c[1]), "+f"(c[2]), "+f"(c[3])
        : "r"(a[0]), "r"(a[1]), "r"(a[2]), "r"(a[3]), "r"(b0), "r"(b1));
}
__device__ __forceinline__ void cpasync16(uint32_t dst, const void* src) {
    asm volatile("cp.async.cg.shared.global [%0], [%1], 16;" :: "r"(dst), "l"(src));
}
// split float2 -> bf16x2 hi + bf16x2 lo
__device__ __forceinline__ void split2(float2 v, uint32_t& h, uint32_t& l) {
    __nv_bfloat162 hb = __floats2bfloat162_rn(v.x, v.y);
    float lx = v.x - __bfloat162float(__low2bfloat16(hb));
    float ly = v.y - __bfloat162float(__high2bfloat16(hb));
    __nv_bfloat162 lb = __floats2bfloat162_rn(lx, ly);
    h = *(uint32_t*)&hb;
    l = *(uint32_t*)&lb;
}
__device__ __forceinline__ void split4(float4 v, uint2& hv, uint2& lv) {
    split2(make_float2(v.x, v.y), hv.x, lv.x);
    split2(make_float2(v.z, v.w), hv.y, lv.y);
}

// ---------------- kernel 1: split emb -> bf16 hi/lo + half-norms ----------------
__global__ void vq_prep(const float* __restrict__ emb) {
    int g = blockIdx.x * blockDim.x + threadIdx.x;
    int w = g >> 5, lane = g & 31;
    if (w >= K_EMB) return;
    float4 v = ((const float4*)emb)[w * 32 + lane];
    float s = v.x * v.x + v.y * v.y + v.z * v.z + v.w * v.w;
    #pragma unroll
    for (int o = 16; o > 0; o >>= 1) s += __shfl_xor_sync(0xffffffffu, s, o);
    if (lane == 0) g_ens[w] = 0.5f * s;
    uint2 hv, lv;
    split4(v, hv, lv);
    ((uint2*)(g_Eh + (size_t)w * D))[lane] = hv;
    ((uint2*)(g_El + (size_t)w * D))[lane] = lv;
}

// ---------------- kernel 2: pipelined HMMA + argmin + gather + loss (fused) ----------------
extern __shared__ char smc[];

__global__ void __launch_bounds__(NTHREADS, 2)
vq_main_kernel(const float* __restrict__ x, const float* __restrict__ emb,
               float* __restrict__ out, int do_loss) {
    const int t = threadIdx.x, wid = t >> 5, lane = t & 31;
    const int row0 = blockIdx.x * BM;
    uint32_t sb = smem_u32(smc);
    float* ens = (float*)(smc + OFF_ENS);
    int*   sIdx = (int*)(smc + OFF_SIDX);
    float* lossp = (float*)(smc + OFF_LOSS);

    #pragma unroll
    for (int i = 0; i < K_EMB / NTHREADS; ++i)
        ens[t + i * NTHREADS] = g_ens[t + i * NTHREADS];

    // ---- A fragments straight from gmem (per-lane MMA layout, split on the fly) ----
    // warp wid owns rows [wid*16, wid*16+16); lane holds rows wid*16 + (lane>>2) and +8
    const int rloc = (lane >> 2);
    const float* xr0 = x + (size_t)(row0 + wid * 16 + rloc) * D;
    const float* xr8 = xr0 + 8 * D;
    uint32_t ah[8][4], al[8][4];
    #pragma unroll
    for (int ks = 0; ks < 8; ++ks) {
        int k0 = ks * 16 + (lane & 3) * 2;
        split2(*(const float2*)(xr0 + k0),     ah[ks][0], al[ks][0]);
        split2(*(const float2*)(xr8 + k0),     ah[ks][1], al[ks][1]);
        split2(*(const float2*)(xr0 + k0 + 8), ah[ks][2], al[ks][2]);
        split2(*(const float2*)(xr8 + k0 + 8), ah[ks][3], al[ks][3]);
    }

    // B fragment addressing: two ldsm rows-sets n0-15 and n16-31
    const int rB = (lane & 7) + ((lane & 16) >> 1);
    const int xorB0 = (rB & 7) << 4, koB = (lane & 8) ? 16 : 0;
    const uint32_t ebR0 = rB * 256, ebR1 = (rB + 16) * 256;
    const int xorB1 = xorB0;   // (rB+16)&7 == rB&7

    auto prefetch = [&](int c, uint32_t bufoff) {
        const char* gh = (const char*)(g_Eh + (size_t)c * BN * D);
        const char* gl = (const char*)(g_El + (size_t)c * BN * D);
        #pragma unroll
        for (int it = 0; it < 2; ++it) {
            int f = t + it * NTHREADS;          // 0..511 16B-units
            int r = f >> 4, u = (f & 15) * 16;
            cpasync16(sb + bufoff + sw(r, u), gh + f * 16);
            cpasync16(sb + bufoff + 8192 + sw(r, u), gl + f * 16);
        }
    };
    prefetch(0, EBUF(0));
    asm volatile("cp.async.commit_group;");
    prefetch(1, EBUF(1));
    asm volatile("cp.async.commit_group;");

    float bS0 = 3.4e38f, bS1 = 3.4e38f;
    int   bI0 = 0,       bI1 = 0;

    for (int c = 0; c < NCHUNK; ++c) {
        asm volatile("cp.async.wait_group 1;");
        __syncthreads();
        const uint32_t eb = sb + EBUF(c & 1);

        float acc[4][4];
        #pragma unroll
        for (int g = 0; g < 4; ++g)
            #pragma unroll
            for (int j = 0; j < 4; ++j) acc[g][j] = 0.f;

        #pragma unroll
        for (int ks = 0; ks < 8; ++ks) {
            int ko = (ks * 32 + koB);
            uint32_t bh0[4], bh1[4], bl0[4], bl1[4];
            ldsm4(bh0, eb + ebR0 + (ko ^ xorB0));
            ldsm4(bh1, eb + ebR1 + (ko ^ xorB1));
            ldsm4(bl0, eb + 8192 + ebR0 + (ko ^ xorB0));
            ldsm4(bl1, eb + 8192 + ebR1 + (ko ^ xorB1));
            mma16816(acc[0], ah[ks], bh0[0], bh0[1]);
            mma16816(acc[1], ah[ks], bh0[2], bh0[3]);
            mma16816(acc[2], ah[ks], bh1[0], bh1[1]);
            mma16816(acc[3], ah[ks], bh1[2], bh1[3]);
            mma16816(acc[0], ah[ks], bl0[0], bl0[1]);
            mma16816(acc[1], ah[ks], bl0[2], bl0[3]);
            mma16816(acc[2], ah[ks], bl1[0], bl1[1]);
            mma16816(acc[3], ah[ks], bl1[2], bl1[3]);
            mma16816(acc[0], al[ks], bh0[0], bh0[1]);
            mma16816(acc[1], al[ks], bh0[2], bh0[3]);
            mma16816(acc[2], al[ks], bh1[0], bh1[1]);
            mma16816(acc[3], al[ks], bh1[2], bh1[3]);
        }
        __syncthreads();
        if (c + 2 < NCHUNK) {
            prefetch(c + 2, EBUF(c & 1));
            asm volatile("cp.async.commit_group;");
        }

        // fold: score = 0.5||e||^2 - x.e ; ascending col order keeps lowest-index ties
        int cbase = c * BN;
        #pragma unroll
        for (int g = 0; g < 4; ++g) {
            int col0 = cbase + g * 8 + (lane & 3) * 2;
            float e0 = ens[col0], e1 = ens[col0 + 1];
            float s00 = e0 - acc[g][0], s01 = e1 - acc[g][1];
            float s10 = e0 - acc[g][2], s11 = e1 - acc[g][3];
            if (s00 < bS0) { bS0 = s00; bI0 = col0; }
            if (s01 < bS0) { bS0 = s01; bI0 = col0 + 1; }
            if (s10 < bS1) { bS1 = s10; bI1 = col0; }
            if (s11 < bS1) { bS1 = s11; bI1 = col0 + 1; }
        }
    }

    // ---- quad reduce (xor 1,2 over lanes holding same row) ----
    #pragma unroll
    for (int o = 1; o <= 2; o <<= 1) {
        float oS = __shfl_xor_sync(0xffffffffu, bS0, o);
        int   oI = __shfl_xor_sync(0xffffffffu, bI0, o);
        if (oS < bS0 || (oS == bS0 && oI < bI0)) { bS0 = oS; bI0 = oI; }
        oS = __shfl_xor_sync(0xffffffffu, bS1, o);
        oI = __shfl_xor_sync(0xffffffffu, bI1, o);
        if (oS < bS1 || (oS == bS1 && oI < bI1)) { bS1 = oS; bI1 = oI; }
    }
    if ((lane & 3) == 0) {
        int row = wid * 16 + rloc;
        sIdx[row] = bI0;
        sIdx[row + 8] = bI1;
    }
    __syncthreads();

    // ---- q gather (exact fp32) + loss partial ----
    const float4* xg = (const float4*)(x + (size_t)row0 * D);
    float lsum = 0.f;
    #pragma unroll
    for (int rr = 0; rr < 16; ++rr) {
        int r  = wid * 16 + rr;
        int bi = sIdx[r];
        float4 e4 = ((const float4*)emb)[bi * 32 + lane];
        float4 x4 = xg[r * 32 + lane];
        float dx = e4.x - x4.x, dy = e4.y - x4.y, dz = e4.z - x4.z, dw = e4.w - x4.w;
        lsum += dx * dx + dy * dy + dz * dz + dw * dw;
        ((float4*)out)[(size_t)(row0 + r) * 32 + lane] = e4;
    }
    if (!do_loss) return;
    #pragma unroll
    for (int o = 16; o > 0; o >>= 1) lsum += __shfl_xor_sync(0xffffffffu, lsum, o);
    if (lane == 0) lossp[wid] = lsum;
    __syncthreads();

    __shared__ unsigned int isLast;
    if (t == 0) {
        float s = 0.f;
        #pragma unroll
        for (int w2 = 0; w2 < 8; ++w2) s += lossp[w2];
        g_partial[blockIdx.x] = s;
        __threadfence();
        unsigned int v = atomicInc(&g_ctr, NBLOCKS - 1);   // wraps to 0: replay-safe
        isLast = (v == NBLOCKS - 1);
    }
    __syncthreads();
    if (!isLast) return;
    __threadfence();
    // deterministic final reduction (fixed index order)
    float* red = lossp;   // reuse 256-float scratch region
    red[t] = g_partial[t];               // NBLOCKS == NTHREADS == 256
    __syncthreads();
    #pragma unroll
    for (int o = NTHREADS / 2; o > 0; o >>= 1) {
        if (t < o) red[t] += red[t + o];
        __syncthreads();
    }
    if (t == 0) out[(long long)NBLOCKS * BM * D] = 1.5f * red[0];
}

// ---------------- launch ----------------
extern "C" void kernel_launch(void* const* d_in, const int* in_sizes, int n_in,
                              void* d_out, int out_size) {
    const float* x = (const float*)d_in[0];
    const float* e = (const float*)d_in[1];
    int nx = in_sizes[0];
    if (n_in >= 2 && in_sizes[0] == K_EMB * D && in_sizes[1] != K_EMB * D) {
        const float* tmp = x; x = e; e = tmp;
        nx = in_sizes[1];
    }
    int N = nx / D;                   // 32768
    int nblocks = N / BM;             // 256
    int do_loss = (out_size > N * D) ? 1 : 0;

    vq_prep<<<K_EMB * 32 / NTHREADS, NTHREADS>>>(e);
    vq_main_kernel<<<nblocks, NTHREADS, SMEM_SZ>>>(x, e, (float*)d_out, do_loss);
}

// round 16
// speedup vs baseline: 1.1015x; 1.1015x over previous
#include <cuda_runtime.h>
#include <cuda_bf16.h>
#include <cstdint>

#define D        128
#define K_EMB    1024
#define BM       128
#define BN       32
#define KSPLIT   4
#define KCODES   (K_EMB / KSPLIT)     // 256 codes per CTA
#define NCHUNK   (KCODES / BN)        // 8 chunks
#define NTHREADS 256
#define NROWTILE 256                  // 32768 / BM
#define NROWS    32768

// main-kernel dynamic smem: E double buffer 2x16KB @0, ens(quarter) 1KB @32768
#define EBUF(b)  ((b) * 16384)
#define OFF_ENS  32768
#define SMEM_SZ  33792

__device__ __nv_bfloat16 g_Eh[K_EMB * D];
__device__ __nv_bfloat16 g_El[K_EMB * D];
__device__ float g_ens[K_EMB];              // 0.5*||e||^2
__device__ float g_pS[KSPLIT * NROWS];      // per-(ksplit,row) partial min score
__device__ int   g_pI[KSPLIT * NROWS];      // per-(ksplit,row) partial argmin
__device__ float g_partial[NROWTILE];
__device__ unsigned int g_ctr;              // zero-init; wrap-safe

// ---------------- helpers ----------------
__device__ __forceinline__ uint32_t smem_u32(const void* p) {
    uint32_t a;
    asm("{ .reg .u64 t; cvta.to.shared.u64 t, %1; cvt.u32.u64 %0, t; }" : "=r"(a) : "l"(p));
    return a;
}
__device__ __forceinline__ int sw(int r, int cb) {       // XOR-16B swizzle, 256B rows
    return r * 256 + (cb ^ ((r & 7) << 4));
}
__device__ __forceinline__ void ldsm4(uint32_t* r, uint32_t addr) {
    asm volatile("ldmatrix.sync.aligned.m8n8.x4.shared.b16 {%0,%1,%2,%3}, [%4];"
                 : "=r"(r[0]), "=r"(r[1]), "=r"(r[2]), "=r"(r[3]) : "r"(addr));
}
__device__ __forceinline__ void mma16816(float* c, const uint32_t* a, uint32_t b0, uint32_t b1) {
    asm volatile(
        "mma.sync.aligned.m16n8k16.row.col.f32.bf16.bf16.f32 "
        "{%0,%1,%2,%3}, {%4,%5,%6,%7}, {%8,%9}, {%0,%1,%2,%3};"
        : "+f"(c[0]), "+f"(c[1]), "+f"(c[2]), "+f"(c[3])
        : "r"(a[0]), "r"(a[1]), "r"(a[2]), "r"(a[3]), "r"(b0), "r"(b1));
}
__device__ __forceinline__ void cpasync16(uint32_t dst, const void* src) {
    asm volatile("cp.async.cg.shared.global [%0], [%1], 16;" :: "r"(dst), "l"(src));
}
__device__ __forceinline__ void split2(float2 v, uint32_t& h, uint32_t& l) {
    __nv_bfloat162 hb = __floats2bfloat162_rn(v.x, v.y);
    float lx = v.x - __bfloat162float(__low2bfloat16(hb));
    float ly = v.y - __bfloat162float(__high2bfloat16(hb));
    __nv_bfloat162 lb = __floats2bfloat162_rn(lx, ly);
    h = *(uint32_t*)&hb;
    l = *(uint32_t*)&lb;
}
__device__ __forceinline__ void split4(float4 v, uint2& hv, uint2& lv) {
    split2(make_float2(v.x, v.y), hv.x, lv.x);
    split2(make_float2(v.z, v.w), hv.y, lv.y);
}

// ---------------- kernel 1: split emb -> bf16 hi/lo + half-norms ----------------
__global__ void vq_prep(const float* __restrict__ emb) {
    int g = blockIdx.x * blockDim.x + threadIdx.x;
    int w = g >> 5, lane = g & 31;
    if (w >= K_EMB) return;
    float4 v = ((const float4*)emb)[w * 32 + lane];
    float s = v.x * v.x + v.y * v.y + v.z * v.z + v.w * v.w;
    #pragma unroll
    for (int o = 16; o > 0; o >>= 1) s += __shfl_xor_sync(0xffffffffu, s, o);
    if (lane == 0) g_ens[w] = 0.5f * s;
    uint2 hv, lv;
    split4(v, hv, lv);
    ((uint2*)(g_Eh + (size_t)w * D))[lane] = hv;
    ((uint2*)(g_El + (size_t)w * D))[lane] = lv;
}

// ---------------- kernel 2: split-K HMMA partial argmin ----------------
extern __shared__ char smc[];

__global__ void __launch_bounds__(NTHREADS, 2)
vq_main_kernel(const float* __restrict__ x) {
    const int t = threadIdx.x, wid = t >> 5, lane = t & 31;
    const int mtile  = blockIdx.x & (NROWTILE - 1);
    const int ksplit = blockIdx.x >> 8;
    const int row0   = mtile * BM;
    const int cbase0 = ksplit * KCODES;
    uint32_t sb = smem_u32(smc);
    float* ens = (float*)(smc + OFF_ENS);

    ens[t] = g_ens[cbase0 + t];          // 256 threads, 256 entries

    // ---- A fragments straight from gmem (per-lane MMA layout, split on the fly) ----
    const int rloc = (lane >> 2);
    const float* xr0 = x + (size_t)(row0 + wid * 16 + rloc) * D;
    const float* xr8 = xr0 + 8 * D;
    uint32_t ah[8][4], al[8][4];
    #pragma unroll
    for (int ks = 0; ks < 8; ++ks) {
        int k0 = ks * 16 + (lane & 3) * 2;
        split2(*(const float2*)(xr0 + k0),     ah[ks][0], al[ks][0]);
        split2(*(const float2*)(xr8 + k0),     ah[ks][1], al[ks][1]);
        split2(*(const float2*)(xr0 + k0 + 8), ah[ks][2], al[ks][2]);
        split2(*(const float2*)(xr8 + k0 + 8), ah[ks][3], al[ks][3]);
    }

    // B fragment addressing
    const int rB = (lane & 7) + ((lane & 16) >> 1);
    const int xorB = (rB & 7) << 4, koB = (lane & 8) ? 16 : 0;
    const uint32_t ebR0 = rB * 256, ebR1 = (rB + 16) * 256;

    auto prefetch = [&](int c, uint32_t bufoff) {
        const char* gh = (const char*)(g_Eh + (size_t)(cbase0 + c * BN) * D);
        const char* gl = (const char*)(g_El + (size_t)(cbase0 + c * BN) * D);
        #pragma unroll
        for (int it = 0; it < 2; ++it) {
            int f = t + it * NTHREADS;          // 0..511 16B-units
            int r = f >> 4, u = (f & 15) * 16;
            cpasync16(sb + bufoff + sw(r, u), gh + f * 16);
            cpasync16(sb + bufoff + 8192 + sw(r, u), gl + f * 16);
        }
    };
    prefetch(0, EBUF(0));
    asm volatile("cp.async.commit_group;");
    prefetch(1, EBUF(1));
    asm volatile("cp.async.commit_group;");

    float bS0 = 3.4e38f, bS1 = 3.4e38f;
    int   bI0 = 0,       bI1 = 0;

    for (int c = 0; c < NCHUNK; ++c) {
        if (c == NCHUNK - 1) asm volatile("cp.async.wait_group 0;");   // race fix
        else                 asm volatile("cp.async.wait_group 1;");
        __syncthreads();
        const uint32_t eb = sb + EBUF(c & 1);

        float acc[4][4];
        #pragma unroll
        for (int g = 0; g < 4; ++g)
            #pragma unroll
            for (int j = 0; j < 4; ++j) acc[g][j] = 0.f;

        #pragma unroll
        for (int ks = 0; ks < 8; ++ks) {
            int ko = (ks * 32 + koB);
            uint32_t bh0[4], bh1[4], bl0[4], bl1[4];
            ldsm4(bh0, eb + ebR0 + (ko ^ xorB));
            ldsm4(bh1, eb + ebR1 + (ko ^ xorB));
            ldsm4(bl0, eb + 8192 + ebR0 + (ko ^ xorB));
            ldsm4(bl1, eb + 8192 + ebR1 + (ko ^ xorB));
            mma16816(acc[0], ah[ks], bh0[0], bh0[1]);
            mma16816(acc[1], ah[ks], bh0[2], bh0[3]);
            mma16816(acc[2], ah[ks], bh1[0], bh1[1]);
            mma16816(acc[3], ah[ks], bh1[2], bh1[3]);
            mma16816(acc[0], ah[ks], bl0[0], bl0[1]);
            mma16816(acc[1], ah[ks], bl0[2], bl0[3]);
            mma16816(acc[2], ah[ks], bl1[0], bl1[1]);
            mma16816(acc[3], ah[ks], bl1[2], bl1[3]);
            mma16816(acc[0], al[ks], bh0[0], bh0[1]);
            mma16816(acc[1], al[ks], bh0[2], bh0[3]);
            mma16816(acc[2], al[ks], bh1[0], bh1[1]);
            mma16816(acc[3], al[ks], bh1[2], bh1[3]);
        }
        __syncthreads();
        if (c + 2 < NCHUNK) {
            prefetch(c + 2, EBUF(c & 1));
            asm volatile("cp.async.commit_group;");
        }

        // fold: score = 0.5||e||^2 - x.e ; ascending local col keeps lowest-index ties
        int cbase = c * BN;
        #pragma unroll
        for (int g = 0; g < 4; ++g) {
            int col0 = cbase + g * 8 + (lane & 3) * 2;
            float e0 = ens[col0], e1 = ens[col0 + 1];
            float s00 = e0 - acc[g][0], s01 = e1 - acc[g][1];
            float s10 = e0 - acc[g][2], s11 = e1 - acc[g][3];
            if (s00 < bS0) { bS0 = s00; bI0 = col0; }
            if (s01 < bS0) { bS0 = s01; bI0 = col0 + 1; }
            if (s10 < bS1) { bS1 = s10; bI1 = col0; }
            if (s11 < bS1) { bS1 = s11; bI1 = col0 + 1; }
        }
    }

    // ---- quad reduce (xor 1,2 over lanes holding same row) ----
    #pragma unroll
    for (int o = 1; o <= 2; o <<= 1) {
        float oS = __shfl_xor_sync(0xffffffffu, bS0, o);
        int   oI = __shfl_xor_sync(0xffffffffu, bI0, o);
        if (oS < bS0 || (oS == bS0 && oI < bI0)) { bS0 = oS; bI0 = oI; }
        oS = __shfl_xor_sync(0xffffffffu, bS1, o);
        oI = __shfl_xor_sync(0xffffffffu, bI1, o);
        if (oS < bS1 || (oS == bS1 && oI < bI1)) { bS1 = oS; bI1 = oI; }
    }
    if ((lane & 3) == 0) {
        int row = row0 + wid * 16 + rloc;
        g_pS[ksplit * NROWS + row]     = bS0;
        g_pI[ksplit * NROWS + row]     = cbase0 + bI0;
        g_pS[ksplit * NROWS + row + 8] = bS1;
        g_pI[ksplit * NROWS + row + 8] = cbase0 + bI1;
    }
}

// ---------------- kernel 3: merge partials + gather + loss ----------------
__global__ void __launch_bounds__(NTHREADS)
vq_epilogue(const float* __restrict__ x, const float* __restrict__ emb,
            float* __restrict__ out, int do_loss) {
    __shared__ int   sIdx[BM];
    __shared__ float lossp[8];
    __shared__ float red[NTHREADS];
    __shared__ unsigned int isLast;

    const int t = threadIdx.x, wid = t >> 5, lane = t & 31;
    const int row0 = blockIdx.x * BM;

    if (t < BM) {
        int row = row0 + t;
        float bs = g_pS[row];
        int   bi = g_pI[row];
        #pragma unroll
        for (int k = 1; k < KSPLIT; ++k) {
            float s = g_pS[k * NROWS + row];
            int   i = g_pI[k * NROWS + row];
            if (s < bs || (s == bs && i < bi)) { bs = s; bi = i; }
        }
        sIdx[t] = bi;
    }
    __syncthreads();

    const float4* xg = (const float4*)(x + (size_t)row0 * D);
    float lsum = 0.f;
    #pragma unroll
    for (int rr = 0; rr < 16; ++rr) {
        int r  = wid * 16 + rr;
        int bi = sIdx[r];
        float4 e4 = ((const float4*)emb)[bi * 32 + lane];
        float4 x4 = xg[r * 32 + lane];
        float dx = e4.x - x4.x, dy = e4.y - x4.y, dz = e4.z - x4.z, dw = e4.w - x4.w;
        lsum += dx * dx + dy * dy + dz * dz + dw * dw;
        ((float4*)out)[(size_t)(row0 + r) * 32 + lane] = e4;
    }
    if (!do_loss) return;
    #pragma unroll
    for (int o = 16; o > 0; o >>= 1) lsum += __shfl_xor_sync(0xffffffffu, lsum, o);
    if (lane == 0) lossp[wid] = lsum;
    __syncthreads();

    if (t == 0) {
        float s = 0.f;
        #pragma unroll
        for (int w2 = 0; w2 < 8; ++w2) s += lossp[w2];
        g_partial[blockIdx.x] = s;
        __threadfence();
        unsigned int v = atomicInc(&g_ctr, NROWTILE - 1);   // wraps: replay-safe
        isLast = (v == NROWTILE - 1);
    }
    __syncthreads();
    if (!isLast) return;
    __threadfence();
    red[t] = g_partial[t];                 // NROWTILE == NTHREADS == 256
    __syncthreads();
    #pragma unroll
    for (int o = NTHREADS / 2; o > 0; o >>= 1) {
        if (t < o) red[t] += red[t + o];
        __syncthreads();
    }
    if (t == 0) out[(long long)NROWS * D] = 1.5f * red[0];  // codebook + BETA*commitment
}

// ---------------- launch ----------------
extern "C" void kernel_launch(void* const* d_in, const int* in_sizes, int n_in,
                              void* d_out, int out_size) {
    const float* x = (const float*)d_in[0];
    const float* e = (const float*)d_in[1];
    int nx = in_sizes[0];
    if (n_in >= 2 && in_sizes[0] == K_EMB * D && in_sizes[1] != K_EMB * D) {
        const float* tmp = x; x = e; e = tmp;
        nx = in_sizes[1];
    }
    int N = nx / D;                        // 32768
    int do_loss = (out_size > N * D) ? 1 : 0;

    vq_prep<<<K_EMB * 32 / NTHREADS, NTHREADS>>>(e);
    vq_main_kernel<<<NROWTILE * KSPLIT, NTHREADS, SMEM_SZ>>>(x);
    vq_epilogue<<<NROWTILE, NTHREADS>>>(x, e, (float*)d_out, do_loss);
}